// round 12
// baseline (speedup 1.0000x reference)
#include <cuda_runtime.h>
#include <math.h>
#include <stdint.h>

// ContrastLoss: B=4, C=4096, K=1.
//
// lse_pairs_b   = log(sum_{lab=0} e^{pred}) + log(sum_{lab=1} e^{-pred})
// loss_contrast = (1/B) * sum_b logaddexp(lse_pairs_b, 0)
// loss_aux      = (1/B) * sum_b mean_c (aux - aux_label)^2
//
// R12: controlled experiment — same 8x512 body as R9 (best), but CLASSIC
// launch (no cluster) to test whether cluster-launch setup carries the
// residual ~0.5-1us. Tail: per-CTA float4 partial to L2 + threadfence +
// atomic ticket; last CTA's warp 0 does a parallel __ldcg reduce.
// Deterministic: fixed slots/order, result independent of finalizer identity.

#define FULL 0xFFFFFFFFu
#define NBLK 8
#define NTHR 512
#define WPB  (NTHR / 32)   // 16 warps per CTA

__device__ float4       g_part[NBLK];
__device__ unsigned int g_ticket = 0;

__device__ __forceinline__ void acc_elem(float v, int lab, float& sn, float& sp) {
    float fl = (float)lab;
    float e  = __expf(v * fmaf(-2.f, fl, 1.f));  // exp(+v) if lab==0 else exp(-v)
    sn = fmaf(e, 1.f - fl, sn);
    sp = fmaf(e, fl, sp);
}

__global__ __launch_bounds__(NTHR, 1)
void contrast_loss_kernel(const float* __restrict__ contrast,
                          const int*   __restrict__ label,
                          const float* __restrict__ aux,
                          const float* __restrict__ aux_label,
                          float* __restrict__ out) {
    __shared__ float4 swarp[WPB];

    int tid = threadIdx.x;
    int blk = blockIdx.x;

    // Each CTA covers 2048 contiguous elements = half of one batch (batch = blk>>1).
    int base = blk * 2048 + tid * 4;

    float4 c  = *reinterpret_cast<const float4*>(contrast + base);
    int4   l  = *reinterpret_cast<const int4*>(label + base);
    float4 a  = *reinterpret_cast<const float4*>(aux + base);
    float4 al = *reinterpret_cast<const float4*>(aux_label + base);

    float sn = 0.f, sp = 0.f, ax = 0.f;

    acc_elem(c.x, l.x, sn, sp);
    acc_elem(c.y, l.y, sn, sp);
    acc_elem(c.z, l.z, sn, sp);
    acc_elem(c.w, l.w, sn, sp);

    float d;
    d = a.x - al.x; ax = fmaf(d, d, ax);
    d = a.y - al.y; ax = fmaf(d, d, ax);
    d = a.z - al.z; ax = fmaf(d, d, ax);
    d = a.w - al.w; ax = fmaf(d, d, ax);

    // Warp reduction (16 warps).
    #pragma unroll
    for (int o = 16; o > 0; o >>= 1) {
        sn += __shfl_down_sync(FULL, sn, o);
        sp += __shfl_down_sync(FULL, sp, o);
        ax += __shfl_down_sync(FULL, ax, o);
    }

    int w = tid >> 5;
    if ((tid & 31) == 0) swarp[w] = make_float4(sn, sp, ax, 0.f);
    __syncthreads();

    if (tid < 32) {
        // Parallel reduce of 16 warp partials (lanes 16-31 contribute zeros).
        float bn = 0.f, bp = 0.f, ba = 0.f;
        if (tid < WPB) {
            float4 p = swarp[tid];
            bn = p.x; bp = p.y; ba = p.z;
        }
        #pragma unroll
        for (int o = 8; o > 0; o >>= 1) {
            bn += __shfl_xor_sync(FULL, bn, o);
            bp += __shfl_xor_sync(FULL, bp, o);
            ba += __shfl_xor_sync(FULL, ba, o);
        }

        // Publish CTA partial; ticket decides the finalizer.
        unsigned int t = 0;
        if (tid == 0) {
            g_part[blk] = make_float4(bn, bp, ba, 0.f);
            __threadfence();                      // release the partial
            t = atomicAdd(&g_ticket, 1u);
        }
        t = __shfl_sync(FULL, t, 0);

        if (t == NBLK - 1) {
            // Last arriver: all partials are L2-visible. Acquire + bypass L1.
            __threadfence();
            float4 q = make_float4(0.f, 0.f, 0.f, 0.f);
            if (tid < NBLK) q = __ldcg(&g_part[tid]);   // lane r -> CTA r

            // Batch b lives in lanes {2b, 2b+1}: one butterfly step.
            float qn = q.x + __shfl_xor_sync(FULL, q.x, 1);
            float qp = q.y + __shfl_xor_sync(FULL, q.y, 1);
            float qa = q.z + __shfl_xor_sync(FULL, q.z, 1);

            // 4 concurrent per-batch loss chains (even lanes 0,2,4,6 valid).
            // Empty class -> qn or qp == 0 -> lse = -inf -> contras = 0.
            float lse     = __logf(qn) + __logf(qp);
            float contras = fmaxf(lse, 0.f) + log1pf(__expf(-fabsf(lse)));
            float laux    = qa * (1.0f / 4096.0f);
            if (tid >= NBLK || (tid & 1)) { contras = 0.f; laux = 0.f; }

            // Sum lanes 0,2,4,6.
            contras += __shfl_xor_sync(FULL, contras, 2);
            laux    += __shfl_xor_sync(FULL, laux, 2);
            contras += __shfl_xor_sync(FULL, contras, 4);
            laux    += __shfl_xor_sync(FULL, laux, 4);

            if (tid == 0) {
                out[0] = contras * 0.25f;   // / n_items (B=4)
                out[1] = laux * 0.25f;
                g_ticket = 0;               // reset for next graph replay
            }
        }
    }
}

extern "C" void kernel_launch(void* const* d_in, const int* in_sizes, int n_in,
                              void* d_out, int out_size) {
    const float* contrast  = (const float*)d_in[0];
    const int*   label     = (const int*)d_in[1];
    const float* aux       = (const float*)d_in[2];
    const float* aux_label = (const float*)d_in[3];
    float* out = (float*)d_out;

    contrast_loss_kernel<<<NBLK, NTHR>>>(contrast, label, aux, aux_label, out);
}

// round 13
// speedup vs baseline: 1.0288x; 1.0288x over previous
#include <cuda_runtime.h>
#include <math.h>
#include <stdint.h>

// ContrastLoss: B=4, C=4096, K=1.
//
// lse_pairs_b   = log(sum_{lab=0} e^{pred}) + log(sum_{lab=1} e^{-pred})
// loss_contrast = (1/B) * sum_b logaddexp(lse_pairs_b, 0)
// loss_aux      = (1/B) * sum_b mean_c (aux - aux_label)^2
//
// R13 = R9 structure (winner of the launch/tail matrix: 8-CTA cluster x 512,
// 4 elems/thread, per-warp DSMEM v4 stores into rank 0, one cluster barrier,
// parallel 128-slot finalize) + body micro-opts:
//   - exp argument sign flip via sign-bit XOR (no I2F/FMA)
//   - class-select accumulation via selects (no label->float convert)
// Deterministic: fixed slots, fixed butterfly order.

#define FULL 0xFFFFFFFFu
#define NBLK 8
#define NTHR 512
#define WPB  (NTHR / 32)            // 16 warps per CTA
#define NSLOT (NBLK * WPB)          // 128 slots

__device__ __forceinline__ uint32_t smem_u32(const void* p) {
    uint32_t a;
    asm("{ .reg .u64 t; cvta.to.shared.u64 t, %1; cvt.u32.u64 %0, t; }"
        : "=r"(a) : "l"(p));
    return a;
}

__device__ __forceinline__ void acc_elem(float v, int lab, float& sn, float& sp) {
    // exp(+v) if lab==0 else exp(-v): flip sign bit when lab==1.
    float t = __int_as_float(__float_as_int(v) ^ (lab << 31));
    float e = __expf(t);
    sn += (lab == 0) ? e : 0.f;
    sp += (lab == 0) ? 0.f : e;
}

__global__ __launch_bounds__(NTHR, 1) __cluster_dims__(NBLK, 1, 1)
void contrast_loss_kernel(const float* __restrict__ contrast,
                          const int*   __restrict__ label,
                          const float* __restrict__ aux,
                          const float* __restrict__ aux_label,
                          float* __restrict__ out) {
    // Identical layout in every CTA; only rank 0's copy is used (mapa
    // translates local slot addresses to rank 0's shared memory).
    __shared__ float4 sclus[NSLOT];

    int tid = threadIdx.x;
    uint32_t rank;
    asm("mov.u32 %0, %%cluster_ctarank;" : "=r"(rank));

    // Each CTA covers 2048 contiguous elements = half of one batch.
    int base = (int)rank * 2048 + tid * 4;

    float4 c  = *reinterpret_cast<const float4*>(contrast + base);
    int4   l  = *reinterpret_cast<const int4*>(label + base);
    float4 a  = *reinterpret_cast<const float4*>(aux + base);
    float4 al = *reinterpret_cast<const float4*>(aux_label + base);

    float sn = 0.f, sp = 0.f, ax = 0.f;

    acc_elem(c.x, l.x, sn, sp);
    acc_elem(c.y, l.y, sn, sp);
    acc_elem(c.z, l.z, sn, sp);
    acc_elem(c.w, l.w, sn, sp);

    float d;
    d = a.x - al.x; ax = fmaf(d, d, ax);
    d = a.y - al.y; ax = fmaf(d, d, ax);
    d = a.z - al.z; ax = fmaf(d, d, ax);
    d = a.w - al.w; ax = fmaf(d, d, ax);

    // Warp reduction (16 warps per CTA).
    #pragma unroll
    for (int o = 16; o > 0; o >>= 1) {
        sn += __shfl_down_sync(FULL, sn, o);
        sp += __shfl_down_sync(FULL, sp, o);
        ax += __shfl_down_sync(FULL, ax, o);
    }

    // Each warp's lane 0 stores its partial DIRECTLY into rank 0's smem.
    if ((tid & 31) == 0) {
        int slot = (int)rank * WPB + (tid >> 5);
        uint32_t local = smem_u32(&sclus[slot]);
        uint32_t rem;
        asm volatile("mapa.shared::cluster.u32 %0, %1, 0;" : "=r"(rem) : "r"(local));
        asm volatile("st.shared::cluster.v4.f32 [%0], {%1, %2, %3, %4};"
                     :: "r"(rem), "f"(sn), "f"(sp), "f"(ax), "f"(0.f) : "memory");
    }

    // One cluster barrier: arrive (release) orders the DSMEM stores;
    // wait (acquire) makes them visible to rank 0's readers.
    asm volatile("barrier.cluster.arrive.aligned;" ::: "memory");
    asm volatile("barrier.cluster.wait.aligned;"   ::: "memory");

    if (rank == 0 && tid < 32) {
        // 128 slots; CTA r (batch r>>1) owns slots [16r, 16r+16), so batch b
        // owns slots [32b, 32b+32). Lane l: batch = l>>3, idx = l&7;
        // reads 4 slots: 32b+idx, +8, +16, +24.
        int b   = tid >> 3;
        int idx = tid & 7;
        float4 p0 = sclus[32 * b + idx];
        float4 p1 = sclus[32 * b + idx + 8];
        float4 p2 = sclus[32 * b + idx + 16];
        float4 p3 = sclus[32 * b + idx + 24];
        float bn = (p0.x + p1.x) + (p2.x + p3.x);
        float bp = (p0.y + p1.y) + (p2.y + p3.y);
        float ba = (p0.z + p1.z) + (p2.z + p3.z);

        // Octet butterfly: lanes within an octet share a batch.
        #pragma unroll
        for (int o = 1; o < 8; o <<= 1) {
            bn += __shfl_xor_sync(FULL, bn, o);
            bp += __shfl_xor_sync(FULL, bp, o);
            ba += __shfl_xor_sync(FULL, ba, o);
        }

        // Per-batch losses computed in parallel across the 4 octets.
        // Empty class -> bn or bp == 0 -> lse = -inf -> contras = 0.
        float lse     = __logf(bn) + __logf(bp);
        float contras = fmaxf(lse, 0.f) + log1pf(__expf(-fabsf(lse)));
        float laux    = ba * (1.0f / 4096.0f);

        // Keep only octet leaders, then butterfly across octets.
        if (idx != 0) { contras = 0.f; laux = 0.f; }
        contras += __shfl_xor_sync(FULL, contras, 8);
        laux    += __shfl_xor_sync(FULL, laux, 8);
        contras += __shfl_xor_sync(FULL, contras, 16);
        laux    += __shfl_xor_sync(FULL, laux, 16);

        if (tid == 0) {
            out[0] = contras * 0.25f;   // / n_items (B=4)
            out[1] = laux * 0.25f;
        }
    }
}

extern "C" void kernel_launch(void* const* d_in, const int* in_sizes, int n_in,
                              void* d_out, int out_size) {
    const float* contrast  = (const float*)d_in[0];
    const int*   label     = (const int*)d_in[1];
    const float* aux       = (const float*)d_in[2];
    const float* aux_label = (const float*)d_in[3];
    float* out = (float*)d_out;

    contrast_loss_kernel<<<NBLK, NTHR>>>(contrast, label, aux, aux_label, out);
}

// round 15
// speedup vs baseline: 1.1088x; 1.0777x over previous
#include <cuda_runtime.h>
#include <math.h>
#include <stdint.h>

// ContrastLoss: B=4, C=4096, K=1.
//
// lse_pairs_b   = log(sum_{lab=0} e^{pred}) + log(sum_{lab=1} e^{-pred})
// loss_contrast = (1/B) * sum_b logaddexp(lse_pairs_b, 0)
// loss_aux      = (1/B) * sum_b mean_c (aux - aux_label)^2
//
// R15 = R9 structure (8-CTA cluster x 512, 4 elems/thread, DSMEM stores into
// rank 0, one cluster barrier, parallel finalize) with a shorter pre-barrier
// critical path: warp reduce stops at octet depth (3 shuffle steps instead
// of 5); 4 octet-leader lanes per warp store 512 total slots; the finalize
// absorbs the extra width with parallel LDS. Deterministic.

#define FULL 0xFFFFFFFFu
#define NBLK 8
#define NTHR 512
#define WPB  (NTHR / 32)              // 16 warps per CTA
#define NSLOT (NBLK * WPB * 4)        // 512 slots (4 octets per warp)

__device__ __forceinline__ uint32_t smem_u32(const void* p) {
    uint32_t a;
    asm("{ .reg .u64 t; cvta.to.shared.u64 t, %1; cvt.u32.u64 %0, t; }"
        : "=r"(a) : "l"(p));
    return a;
}

__device__ __forceinline__ void acc_elem(float v, int lab, float& sn, float& sp) {
    // exp(+v) if lab==0 else exp(-v): flip the sign bit when lab==1.
    float t = __int_as_float(__float_as_int(v) ^ (lab << 31));
    float e = __expf(t);
    sn += (lab == 0) ? e : 0.f;
    sp += (lab == 0) ? 0.f : e;
}

__global__ __launch_bounds__(NTHR, 1) __cluster_dims__(NBLK, 1, 1)
void contrast_loss_kernel(const float* __restrict__ contrast,
                          const int*   __restrict__ label,
                          const float* __restrict__ aux,
                          const float* __restrict__ aux_label,
                          float* __restrict__ out) {
    // Identical layout in every CTA; only rank 0's copy is used (mapa
    // translates local slot addresses to rank 0's shared memory).
    __shared__ float4 sclus[NSLOT];

    int tid = threadIdx.x;
    uint32_t rank;
    asm("mov.u32 %0, %%cluster_ctarank;" : "=r"(rank));

    // Each CTA covers 2048 contiguous elements = half of one batch.
    int base = (int)rank * 2048 + tid * 4;

    float4 c  = *reinterpret_cast<const float4*>(contrast + base);
    int4   l  = *reinterpret_cast<const int4*>(label + base);
    float4 a  = *reinterpret_cast<const float4*>(aux + base);
    float4 al = *reinterpret_cast<const float4*>(aux_label + base);

    float sn = 0.f, sp = 0.f, ax = 0.f;

    acc_elem(c.x, l.x, sn, sp);
    acc_elem(c.y, l.y, sn, sp);
    acc_elem(c.z, l.z, sn, sp);
    acc_elem(c.w, l.w, sn, sp);

    float d;
    d = a.x - al.x; ax = fmaf(d, d, ax);
    d = a.y - al.y; ax = fmaf(d, d, ax);
    d = a.z - al.z; ax = fmaf(d, d, ax);
    d = a.w - al.w; ax = fmaf(d, d, ax);

    // Octet-depth reduce: 3 butterfly steps; every 8-lane octet holds its sum.
    #pragma unroll
    for (int o = 1; o < 8; o <<= 1) {
        sn += __shfl_xor_sync(FULL, sn, o);
        sp += __shfl_xor_sync(FULL, sp, o);
        ax += __shfl_xor_sync(FULL, ax, o);
    }

    // 4 octet-leader lanes per warp store partials into rank 0's smem.
    if ((tid & 7) == 0) {
        int slot = (int)rank * (WPB * 4) + ((tid >> 5) << 2) + ((tid >> 3) & 3);
        uint32_t local = smem_u32(&sclus[slot]);
        uint32_t rem;
        asm volatile("mapa.shared::cluster.u32 %0, %1, 0;" : "=r"(rem) : "r"(local));
        asm volatile("st.shared::cluster.v4.f32 [%0], {%1, %2, %3, %4};"
                     :: "r"(rem), "f"(sn), "f"(sp), "f"(ax), "f"(0.f) : "memory");
    }

    // One cluster barrier: arrive (release) orders the DSMEM stores;
    // wait (acquire) makes them visible to rank 0's readers.
    asm volatile("barrier.cluster.arrive.aligned;" ::: "memory");
    asm volatile("barrier.cluster.wait.aligned;"   ::: "memory");

    if (rank == 0 && tid < 32) {
        // 512 slots; CTA r owns [64r, 64r+64) -> batch b owns [128b, 128b+128).
        // Lane l: batch = l>>3, idx = l&7; reads 16 slots 128b + idx + 8k.
        int b   = tid >> 3;
        int idx = tid & 7;
        const float4* sb = &sclus[128 * b + idx];
        float bn = 0.f, bp = 0.f, ba = 0.f;
        #pragma unroll
        for (int k = 0; k < 16; k++) {
            float4 p = sb[8 * k];
            bn += p.x; bp += p.y; ba += p.z;
        }

        // Octet butterfly: lanes within an octet share a batch.
        #pragma unroll
        for (int o = 1; o < 8; o <<= 1) {
            bn += __shfl_xor_sync(FULL, bn, o);
            bp += __shfl_xor_sync(FULL, bp, o);
            ba += __shfl_xor_sync(FULL, ba, o);
        }

        // Per-batch losses computed in parallel across the 4 octets.
        // Empty class -> bn or bp == 0 -> lse = -inf -> contras = 0.
        float lse     = __logf(bn) + __logf(bp);
        float contras = fmaxf(lse, 0.f) + log1pf(__expf(-fabsf(lse)));
        float laux    = ba * (1.0f / 4096.0f);

        // Keep only octet leaders, then butterfly across octets.
        if (idx != 0) { contras = 0.f; laux = 0.f; }
        contras += __shfl_xor_sync(FULL, contras, 8);
        laux    += __shfl_xor_sync(FULL, laux, 8);
        contras += __shfl_xor_sync(FULL, contras, 16);
        laux    += __shfl_xor_sync(FULL, laux, 16);

        if (tid == 0) {
            out[0] = contras * 0.25f;   // / n_items (B=4)
            out[1] = laux * 0.25f;
        }
    }
}

extern "C" void kernel_launch(void* const* d_in, const int* in_sizes, int n_in,
                              void* d_out, int out_size) {
    const float* contrast  = (const float*)d_in[0];
    const int*   label     = (const int*)d_in[1];
    const float* aux       = (const float*)d_in[2];
    const float* aux_label = (const float*)d_in[3];
    float* out = (float*)d_out;

    contrast_loss_kernel<<<NBLK, NTHR>>>(contrast, label, aux, aux_label, out);
}